// round 3
// baseline (speedup 1.0000x reference)
#include <cuda_runtime.h>
#include <cmath>
#include <cstdint>

#define B_   8
#define C_   64
#define H_   128
#define W_   128
#define HW_  (H_*W_)
#define NS_  3

__device__ float g_xT[(size_t)B_*HW_*C_];        // x as [b][i][j][c]
__device__ float g_y [(size_t)NS_*B_*C_*HW_];    // y per scale [s][b][o][i][j]
__device__ float g_part[NS_*1024*64*2];          // per (s, b*128+i) partial (sum,sumsq)
__device__ float g_ab[NS_*64*2];                 // per (s,o): scale a, shift b

#define OFF_WP    0        // 9*64*20 = 11520 (phase1)  } aliased with
#define OFF_XOFF  0        // 128*68  =  8704 (phase2+) } each other
#define OFF_TILE  11520    // 3*16*130 = 6240
#define OFF_WC    17760    // 4096
#define OFF_SV    21856    // 9*128 (int)
#define OFF_SFX   23008    // 9*128
#define OFF_SFY   24160    // 9*128
#define OFF_RED   25312    // 512
#define SMEM_FLOATS 25824
#define SMEM_BYTES  (SMEM_FLOATS*4)

#define CONV_FMA(xs, wptr) do {                                              \
    float4 a0 = *(const float4*)((wptr));                                    \
    float4 a1 = *(const float4*)((wptr)+4);                                  \
    float4 a2 = *(const float4*)((wptr)+8);                                  \
    float4 a3 = *(const float4*)((wptr)+12);                                 \
    float2 a4 = *(const float2*)((wptr)+16);                                 \
    acc[0] +=(xs)*a0.x; acc[1] +=(xs)*a0.y; acc[2] +=(xs)*a0.z; acc[3] +=(xs)*a0.w; \
    acc[4] +=(xs)*a1.x; acc[5] +=(xs)*a1.y; acc[6] +=(xs)*a1.z; acc[7] +=(xs)*a1.w; \
    acc[8] +=(xs)*a2.x; acc[9] +=(xs)*a2.y; acc[10]+=(xs)*a2.z; acc[11]+=(xs)*a2.w; \
    acc[12]+=(xs)*a3.x; acc[13]+=(xs)*a3.y; acc[14]+=(xs)*a3.z; acc[15]+=(xs)*a3.w; \
    acc[16]+=(xs)*a4.x; acc[17]+=(xs)*a4.y; } while(0)

__global__ void k_transpose(const float* __restrict__ x) {
    __shared__ float tile[64*129];
    int bi = blockIdx.x;                 // b*128+i
    int b = bi >> 7, i = bi & 127;
    int tid = threadIdx.x;
    const float* src = x + (size_t)b*C_*HW_ + (size_t)i*W_;
    for (int idx = tid; idx < 64*128; idx += 256) {
        int c = idx >> 7, j = idx & 127;
        tile[c*129 + j] = src[(size_t)c*HW_ + j];
    }
    __syncthreads();
    float* dst = g_xT + (size_t)bi * 128 * 64;
    for (int idx = tid; idx < 64*128; idx += 256) {
        int j = idx >> 6, c = idx & 63;
        dst[(size_t)j*64 + c] = tile[c*129 + j];
    }
}

__global__ __launch_bounds__(128)
void k_main(const float* __restrict__ Wp, const float* __restrict__ bp,
            const float* __restrict__ Wc) {
    extern __shared__ float SM[];
    const int i = blockIdx.x, b = blockIdx.y, s = blockIdx.z;
    const int tid = threadIdx.x;
    const int j = tid;

    float* wp_s  = SM + OFF_WP;     // [tap][c][20]
    float* tileS = SM + OFF_TILE;   // [3][16][130]
    float* xoff_s= SM + OFF_XOFF;   // [128][68]
    float* wc_s  = SM + OFF_WC;     // [o][c]
    int*   sv    = (int*)(SM + OFF_SV);
    float* sfx   = SM + OFF_SFX;
    float* sfy   = SM + OFF_SFY;
    float* red   = SM + OFF_RED;

    // stage weights
    for (int idx = tid; idx < 18*64*9; idx += 128) {
        int o = idx / 576, r = idx % 576, c = r / 9, tap = r % 9;
        wp_s[tap*1280 + c*20 + o] = Wp[s*10368 + idx];
    }
    for (int idx = tid; idx < 64*64; idx += 128)
        wc_s[idx] = Wc[s*4096 + idx];

    const float* xTb = g_xT + (size_t)b * HW_ * 64;

    // phase 1: 3x3 conv 64->18 (offsets)
    float acc[18];
#pragma unroll
    for (int o = 0; o < 18; o++) acc[o] = 0.f;

#pragma unroll 1
    for (int chunk = 0; chunk < 4; chunk++) {
        __syncthreads();
        for (int p = tid; p < 3*130; p += 128) {
            int r = p / 130, col = p % 130;
            int rr = i + r - 1, jj = col - 1;
            float4 v0 = make_float4(0,0,0,0), v1 = v0, v2 = v0, v3 = v0;
            if ((unsigned)rr < 128u && (unsigned)jj < 128u) {
                const float4* sp = (const float4*)(xTb + ((size_t)rr*128 + jj)*64 + chunk*16);
                v0 = sp[0]; v1 = sp[1]; v2 = sp[2]; v3 = sp[3];
            }
            float vals[16] = {v0.x,v0.y,v0.z,v0.w, v1.x,v1.y,v1.z,v1.w,
                              v2.x,v2.y,v2.z,v2.w, v3.x,v3.y,v3.z,v3.w};
            float* t = tileS + r*16*130 + col;
#pragma unroll
            for (int cc = 0; cc < 16; cc++) t[cc*130] = vals[cc];
        }
        __syncthreads();
#pragma unroll 1
        for (int ky = 0; ky < 3; ky++) {
#pragma unroll 1
            for (int kx = 0; kx < 3; kx++) {
                const float* wt   = wp_s + (ky*3 + kx)*1280 + chunk*16*20;
                const float* trow = tileS + ky*16*130 + (j + kx);
#pragma unroll
                for (int cc = 0; cc < 16; cc++) {
                    float xs = trow[cc*130];
                    CONV_FMA(xs, wt + cc*20);
                }
            }
        }
    }

    // phase 1b: sample points
    {
        const float scl = (float)(s + 1);
#pragma unroll
        for (int n = 0; n < 9; n++) {
            float ox = (acc[n]     + bp[s*18 + n])     * scl;
            float oy = (acc[9 + n] + bp[s*18 + 9 + n]) * scl;
            float px = (float)(i + n/3) + ox;
            float py = (float)(j + n%3) + oy;
            float fxf = floorf(px), fyf = floorf(py);
            sv [n*128 + j] = (int)fxf * 128 + (int)fyf;
            sfx[n*128 + j] = px - fxf;
            sfy[n*128 + j] = py - fyf;
        }
    }
    __syncthreads();

    // phase 2: bilinear gather (warp per 32 positions, 16 lanes = 64 ch, 2 corners/half)
    {
        const int lane = tid & 31, wrp = tid >> 5;
        const int grp  = lane >> 4;            // 0: lt+lb, 1: rb+rt
        const int cq   = (lane & 15) * 4;
        const int d1 = grp ? 129 : 0;
        const int d2 = grp ? 128 : 1;
        for (int t = 0; t < 32; t++) {
            const int q = wrp*32 + t;
            float4 acc4 = make_float4(0,0,0,0);
#pragma unroll
            for (int n = 0; n < 9; n++) {
                int   v  = sv [n*128 + q];
                float fx = sfx[n*128 + q];
                float fy = sfy[n*128 + q];
                float ax  = grp ? fx       : 1.f - fx;
                float ay1 = grp ? fy       : 1.f - fy;
                float ay2 = grp ? 1.f - fy : fy;
                int i1 = v + d1; i1 = min(max(i1, 0), HW_ - 1);
                int i2 = v + d2; i2 = min(max(i2, 0), HW_ - 1);
                float4 t1 = *(const float4*)(xTb + (size_t)i1*64 + cq);
                float4 t2 = *(const float4*)(xTb + (size_t)i2*64 + cq);
                float w1 = ax * ay1, w2 = ax * ay2;
                acc4.x += w1*t1.x + w2*t2.x;
                acc4.y += w1*t1.y + w2*t2.y;
                acc4.z += w1*t1.z + w2*t2.z;
                acc4.w += w1*t1.w + w2*t2.w;
            }
            acc4.x += __shfl_xor_sync(0xffffffffu, acc4.x, 16);
            acc4.y += __shfl_xor_sync(0xffffffffu, acc4.y, 16);
            acc4.z += __shfl_xor_sync(0xffffffffu, acc4.z, 16);
            acc4.w += __shfl_xor_sync(0xffffffffu, acc4.w, 16);
            if (grp == 0) {
                const float k9 = 1.f / 9.f;
                float4 r = make_float4(acc4.x*k9, acc4.y*k9, acc4.z*k9, acc4.w*k9);
                *(float4*)(xoff_s + q*68 + cq) = r;
            }
        }
    }
    __syncthreads();

    // phase 3: channel mix + y store + BN partials
    {
        float xo[64];
        const float* xr = xoff_s + (size_t)tid * 68;
#pragma unroll
        for (int c4 = 0; c4 < 16; c4++) {
            float4 v = *(const float4*)(xr + c4*4);
            xo[c4*4+0] = v.x; xo[c4*4+1] = v.y; xo[c4*4+2] = v.z; xo[c4*4+3] = v.w;
        }
        const size_t ybase = ((size_t)(s*8 + b) * 64) * HW_ + (size_t)i*W_ + j;
        const int lane = tid & 31, wrp = tid >> 5;
#pragma unroll 1
        for (int o = 0; o < 64; o++) {
            float yv = 0.f;
#pragma unroll
            for (int c4 = 0; c4 < 16; c4++) {
                float4 wv = *(const float4*)(wc_s + o*64 + c4*4);
                yv += wv.x*xo[c4*4] + wv.y*xo[c4*4+1] + wv.z*xo[c4*4+2] + wv.w*xo[c4*4+3];
            }
            g_y[ybase + (size_t)o * HW_] = yv;
            float s1 = yv, s2 = yv * yv;
#pragma unroll
            for (int d = 16; d > 0; d >>= 1) {
                s1 += __shfl_xor_sync(0xffffffffu, s1, d);
                s2 += __shfl_xor_sync(0xffffffffu, s2, d);
            }
            if (lane == 0) { red[(wrp*64 + o)*2 + 0] = s1; red[(wrp*64 + o)*2 + 1] = s2; }
        }
        __syncthreads();
        if (tid < 128) {
            int o = tid & 63, t = tid >> 6;
            float sum = red[(0*64 + o)*2 + t] + red[(1*64 + o)*2 + t]
                      + red[(2*64 + o)*2 + t] + red[(3*64 + o)*2 + t];
            g_part[(((s*1024) + (b*128 + i))*64 + o)*2 + t] = sum;
        }
    }
}

__global__ void k_stats(const float* __restrict__ gamma, const float* __restrict__ beta) {
    const int o = blockIdx.x, s = blockIdx.y, tid = threadIdx.x;  // 256 threads
    __shared__ float r1[256], r2[256];
    float s1 = 0.f, s2 = 0.f;
    for (int blk = tid; blk < 1024; blk += 256) {
        const float* p = g_part + (((s*1024) + blk)*64 + o)*2;
        s1 += p[0]; s2 += p[1];
    }
    r1[tid] = s1; r2[tid] = s2; __syncthreads();
    for (int d = 128; d > 0; d >>= 1) {
        if (tid < d) { r1[tid] += r1[tid + d]; r2[tid] += r2[tid + d]; }
        __syncthreads();
    }
    if (tid == 0) {
        const float M = 131072.f;
        float mu  = r1[0] / M;
        float var = r2[0] / M - mu*mu;
        float inv = 1.f / sqrtf(var + 1e-5f);
        float a  = gamma[s*64 + o] * inv;
        float bb = beta [s*64 + o] - mu * a;
        g_ab[(s*64 + o)*2 + 0] = a;
        g_ab[(s*64 + o)*2 + 1] = bb;
    }
}

__global__ void k_final(float* __restrict__ out) {
    int i4 = blockIdx.x * blockDim.x + threadIdx.x;
    if (i4 >= (B_*C_*HW_)/4) return;
    size_t e = (size_t)i4 * 4;
    int c = ((int)(e >> 14)) & 63;
    float4 o4 = make_float4(0,0,0,0);
#pragma unroll
    for (int s = 0; s < 3; s++) {
        float a  = g_ab[(s*64 + c)*2 + 0];
        float bb = g_ab[(s*64 + c)*2 + 1];
        float4 y4 = *(const float4*)(g_y + (size_t)s * ((size_t)B_*C_*HW_) + e);
        float z;
        z = a*y4.x + bb; o4.x += z / (1.f + expf(-z));
        z = a*y4.y + bb; o4.y += z / (1.f + expf(-z));
        z = a*y4.z + bb; o4.z += z / (1.f + expf(-z));
        z = a*y4.w + bb; o4.w += z / (1.f + expf(-z));
    }
    const float k = 1.f / 3.f;
    o4.x *= k; o4.y *= k; o4.z *= k; o4.w *= k;
    *(float4*)(out + e) = o4;
}

extern "C" void kernel_launch(void* const* d_in, const int* in_sizes, int n_in,
                              void* d_out, int out_size) {
    (void)in_sizes; (void)n_in; (void)out_size;
    const float* x     = (const float*)d_in[0];
    const float* Wp    = (const float*)d_in[1];
    const float* bp    = (const float*)d_in[2];
    const float* Wc    = (const float*)d_in[3];
    const float* gamma = (const float*)d_in[4];
    const float* beta  = (const float*)d_in[5];
    float* out = (float*)d_out;

    cudaFuncSetAttribute(k_main, cudaFuncAttributeMaxDynamicSharedMemorySize, SMEM_BYTES);

    k_transpose<<<B_*H_, 256>>>(x);
    dim3 gmain(H_, B_, NS_);
    k_main<<<gmain, 128, SMEM_BYTES>>>(Wp, bp, Wc);
    dim3 gstats(64, NS_);
    k_stats<<<gstats, 256>>>(gamma, beta);
    int n4 = (B_*C_*HW_) / 4;
    k_final<<<(n4 + 255) / 256, 256>>>(out);
}

// round 4
// speedup vs baseline: 1.0023x; 1.0023x over previous
#include <cuda_runtime.h>
#include <cmath>
#include <cstdint>

#define B_   8
#define C_   64
#define H_   128
#define W_   128
#define HW_  (H_*W_)
#define NS_  3

__device__ float g_xT[(size_t)B_*HW_*C_];        // x as [b][i][j][c]
__device__ float g_y [(size_t)NS_*B_*C_*HW_];    // y per scale [s][b][o][i][j]
__device__ float g_part[NS_*1024*64*2];          // per (s, b*128+i) partial (sum,sumsq)
__device__ float g_ab[NS_*64*2];                 // per (s,o): scale a, shift b

#define OFF_WP    0        // 9*64*20 = 11520 (phase1)  } aliased with
#define OFF_XOFF  0        // 128*68  =  8704 (phase2+) } each other
#define OFF_TILE  11520    // 3*16*130 = 6240
#define OFF_WC    17760    // 4096
#define OFF_SV    21856    // 9*128 (int)
#define OFF_SFX   23008    // 9*128
#define OFF_SFY   24160    // 9*128
#define OFF_RED   25312    // 512
#define SMEM_FLOATS 25824
#define SMEM_BYTES  (SMEM_FLOATS*4)

#define CONV_FMA(xs, wptr) do {                                              \
    float4 a0 = *(const float4*)((wptr));                                    \
    float4 a1 = *(const float4*)((wptr)+4);                                  \
    float4 a2 = *(const float4*)((wptr)+8);                                  \
    float4 a3 = *(const float4*)((wptr)+12);                                 \
    float2 a4 = *(const float2*)((wptr)+16);                                 \
    acc[0] +=(xs)*a0.x; acc[1] +=(xs)*a0.y; acc[2] +=(xs)*a0.z; acc[3] +=(xs)*a0.w; \
    acc[4] +=(xs)*a1.x; acc[5] +=(xs)*a1.y; acc[6] +=(xs)*a1.z; acc[7] +=(xs)*a1.w; \
    acc[8] +=(xs)*a2.x; acc[9] +=(xs)*a2.y; acc[10]+=(xs)*a2.z; acc[11]+=(xs)*a2.w; \
    acc[12]+=(xs)*a3.x; acc[13]+=(xs)*a3.y; acc[14]+=(xs)*a3.z; acc[15]+=(xs)*a3.w; \
    acc[16]+=(xs)*a4.x; acc[17]+=(xs)*a4.y; } while(0)

__global__ void k_transpose(const float* __restrict__ x) {
    __shared__ float tile[64*129];
    int bi = blockIdx.x;                 // b*128+i
    int b = bi >> 7, i = bi & 127;
    int tid = threadIdx.x;
    const float* src = x + (size_t)b*C_*HW_ + (size_t)i*W_;
    for (int idx = tid; idx < 64*128; idx += 256) {
        int c = idx >> 7, j = idx & 127;
        tile[c*129 + j] = src[(size_t)c*HW_ + j];
    }
    __syncthreads();
    float* dst = g_xT + (size_t)bi * 128 * 64;
    for (int idx = tid; idx < 64*128; idx += 256) {
        int j = idx >> 6, c = idx & 63;
        dst[(size_t)j*64 + c] = tile[c*129 + j];
    }
}

__global__ __launch_bounds__(128)
void k_main(const float* __restrict__ Wp, const float* __restrict__ bp,
            const float* __restrict__ Wc) {
    extern __shared__ float SM[];
    const int i = blockIdx.x, b = blockIdx.y, s = blockIdx.z;
    const int tid = threadIdx.x;
    const int j = tid;

    float* wp_s  = SM + OFF_WP;     // [tap][c][20]
    float* tileS = SM + OFF_TILE;   // [3][16][130]
    float* xoff_s= SM + OFF_XOFF;   // [128][68]
    float* wc_s  = SM + OFF_WC;     // [o][c]
    int*   sv    = (int*)(SM + OFF_SV);
    float* sfx   = SM + OFF_SFX;
    float* sfy   = SM + OFF_SFY;
    float* red   = SM + OFF_RED;

    // stage weights
    for (int idx = tid; idx < 18*64*9; idx += 128) {
        int o = idx / 576, r = idx % 576, c = r / 9, tap = r % 9;
        wp_s[tap*1280 + c*20 + o] = Wp[s*10368 + idx];
    }
    for (int idx = tid; idx < 64*64; idx += 128)
        wc_s[idx] = Wc[s*4096 + idx];

    const float* xTb = g_xT + (size_t)b * HW_ * 64;

    // phase 1: 3x3 conv 64->18 (offsets)
    float acc[18];
#pragma unroll
    for (int o = 0; o < 18; o++) acc[o] = 0.f;

#pragma unroll 1
    for (int chunk = 0; chunk < 4; chunk++) {
        __syncthreads();
        for (int p = tid; p < 3*130; p += 128) {
            int r = p / 130, col = p % 130;
            int rr = i + r - 1, jj = col - 1;
            float4 v0 = make_float4(0,0,0,0), v1 = v0, v2 = v0, v3 = v0;
            if ((unsigned)rr < 128u && (unsigned)jj < 128u) {
                const float4* sp = (const float4*)(xTb + ((size_t)rr*128 + jj)*64 + chunk*16);
                v0 = sp[0]; v1 = sp[1]; v2 = sp[2]; v3 = sp[3];
            }
            float vals[16] = {v0.x,v0.y,v0.z,v0.w, v1.x,v1.y,v1.z,v1.w,
                              v2.x,v2.y,v2.z,v2.w, v3.x,v3.y,v3.z,v3.w};
            float* t = tileS + r*16*130 + col;
#pragma unroll
            for (int cc = 0; cc < 16; cc++) t[cc*130] = vals[cc];
        }
        __syncthreads();
#pragma unroll 1
        for (int ky = 0; ky < 3; ky++) {
#pragma unroll 1
            for (int kx = 0; kx < 3; kx++) {
                const float* wt   = wp_s + (ky*3 + kx)*1280 + chunk*16*20;
                const float* trow = tileS + ky*16*130 + (j + kx);
#pragma unroll
                for (int cc = 0; cc < 16; cc++) {
                    float xs = trow[cc*130];
                    CONV_FMA(xs, wt + cc*20);
                }
            }
        }
    }

    // phase 1b: sample points
    {
        const float scl = (float)(s + 1);
#pragma unroll
        for (int n = 0; n < 9; n++) {
            float ox = (acc[n]     + bp[s*18 + n])     * scl;
            float oy = (acc[9 + n] + bp[s*18 + 9 + n]) * scl;
            float px = (float)(i + n/3) + ox;
            float py = (float)(j + n%3) + oy;
            float fxf = floorf(px), fyf = floorf(py);
            sv [n*128 + j] = (int)fxf * 128 + (int)fyf;
            sfx[n*128 + j] = px - fxf;
            sfy[n*128 + j] = py - fyf;
        }
    }
    __syncthreads();

    // phase 2: bilinear gather (warp per 32 positions, 16 lanes = 64 ch, 2 corners/half)
    {
        const int lane = tid & 31, wrp = tid >> 5;
        const int grp  = lane >> 4;            // 0: lt+lb, 1: rb+rt
        const int cq   = (lane & 15) * 4;
        const int d1 = grp ? 129 : 0;
        const int d2 = grp ? 128 : 1;
        for (int t = 0; t < 32; t++) {
            const int q = wrp*32 + t;
            float4 acc4 = make_float4(0,0,0,0);
#pragma unroll
            for (int n = 0; n < 9; n++) {
                int   v  = sv [n*128 + q];
                float fx = sfx[n*128 + q];
                float fy = sfy[n*128 + q];
                float ax  = grp ? fx       : 1.f - fx;
                float ay1 = grp ? fy       : 1.f - fy;
                float ay2 = grp ? 1.f - fy : fy;
                int i1 = v + d1; i1 = min(max(i1, 0), HW_ - 1);
                int i2 = v + d2; i2 = min(max(i2, 0), HW_ - 1);
                float4 t1 = *(const float4*)(xTb + (size_t)i1*64 + cq);
                float4 t2 = *(const float4*)(xTb + (size_t)i2*64 + cq);
                float w1 = ax * ay1, w2 = ax * ay2;
                acc4.x += w1*t1.x + w2*t2.x;
                acc4.y += w1*t1.y + w2*t2.y;
                acc4.z += w1*t1.z + w2*t2.z;
                acc4.w += w1*t1.w + w2*t2.w;
            }
            acc4.x += __shfl_xor_sync(0xffffffffu, acc4.x, 16);
            acc4.y += __shfl_xor_sync(0xffffffffu, acc4.y, 16);
            acc4.z += __shfl_xor_sync(0xffffffffu, acc4.z, 16);
            acc4.w += __shfl_xor_sync(0xffffffffu, acc4.w, 16);
            if (grp == 0) {
                const float k9 = 1.f / 9.f;
                float4 r = make_float4(acc4.x*k9, acc4.y*k9, acc4.z*k9, acc4.w*k9);
                *(float4*)(xoff_s + q*68 + cq) = r;
            }
        }
    }
    __syncthreads();

    // phase 3: channel mix + y store + BN partials
    {
        float xo[64];
        const float* xr = xoff_s + (size_t)tid * 68;
#pragma unroll
        for (int c4 = 0; c4 < 16; c4++) {
            float4 v = *(const float4*)(xr + c4*4);
            xo[c4*4+0] = v.x; xo[c4*4+1] = v.y; xo[c4*4+2] = v.z; xo[c4*4+3] = v.w;
        }
        const size_t ybase = ((size_t)(s*8 + b) * 64) * HW_ + (size_t)i*W_ + j;
        const int lane = tid & 31, wrp = tid >> 5;
#pragma unroll 1
        for (int o = 0; o < 64; o++) {
            float yv = 0.f;
#pragma unroll
            for (int c4 = 0; c4 < 16; c4++) {
                float4 wv = *(const float4*)(wc_s + o*64 + c4*4);
                yv += wv.x*xo[c4*4] + wv.y*xo[c4*4+1] + wv.z*xo[c4*4+2] + wv.w*xo[c4*4+3];
            }
            g_y[ybase + (size_t)o * HW_] = yv;
            float s1 = yv, s2 = yv * yv;
#pragma unroll
            for (int d = 16; d > 0; d >>= 1) {
                s1 += __shfl_xor_sync(0xffffffffu, s1, d);
                s2 += __shfl_xor_sync(0xffffffffu, s2, d);
            }
            if (lane == 0) { red[(wrp*64 + o)*2 + 0] = s1; red[(wrp*64 + o)*2 + 1] = s2; }
        }
        __syncthreads();
        if (tid < 128) {
            int o = tid & 63, t = tid >> 6;
            float sum = red[(0*64 + o)*2 + t] + red[(1*64 + o)*2 + t]
                      + red[(2*64 + o)*2 + t] + red[(3*64 + o)*2 + t];
            g_part[(((s*1024) + (b*128 + i))*64 + o)*2 + t] = sum;
        }
    }
}

__global__ void k_stats(const float* __restrict__ gamma, const float* __restrict__ beta) {
    const int o = blockIdx.x, s = blockIdx.y, tid = threadIdx.x;  // 256 threads
    __shared__ float r1[256], r2[256];
    float s1 = 0.f, s2 = 0.f;
    for (int blk = tid; blk < 1024; blk += 256) {
        const float* p = g_part + (((s*1024) + blk)*64 + o)*2;
        s1 += p[0]; s2 += p[1];
    }
    r1[tid] = s1; r2[tid] = s2; __syncthreads();
    for (int d = 128; d > 0; d >>= 1) {
        if (tid < d) { r1[tid] += r1[tid + d]; r2[tid] += r2[tid + d]; }
        __syncthreads();
    }
    if (tid == 0) {
        const float M = 131072.f;
        float mu  = r1[0] / M;
        float var = r2[0] / M - mu*mu;
        float inv = 1.f / sqrtf(var + 1e-5f);
        float a  = gamma[s*64 + o] * inv;
        float bb = beta [s*64 + o] - mu * a;
        g_ab[(s*64 + o)*2 + 0] = a;
        g_ab[(s*64 + o)*2 + 1] = bb;
    }
}

__global__ void k_final(float* __restrict__ out) {
    int i4 = blockIdx.x * blockDim.x + threadIdx.x;
    if (i4 >= (B_*C_*HW_)/4) return;
    size_t e = (size_t)i4 * 4;
    int c = ((int)(e >> 14)) & 63;
    float4 o4 = make_float4(0,0,0,0);
#pragma unroll
    for (int s = 0; s < 3; s++) {
        float a  = g_ab[(s*64 + c)*2 + 0];
        float bb = g_ab[(s*64 + c)*2 + 1];
        float4 y4 = *(const float4*)(g_y + (size_t)s * ((size_t)B_*C_*HW_) + e);
        float z;
        z = a*y4.x + bb; o4.x += z / (1.f + expf(-z));
        z = a*y4.y + bb; o4.y += z / (1.f + expf(-z));
        z = a*y4.z + bb; o4.z += z / (1.f + expf(-z));
        z = a*y4.w + bb; o4.w += z / (1.f + expf(-z));
    }
    const float k = 1.f / 3.f;
    o4.x *= k; o4.y *= k; o4.z *= k; o4.w *= k;
    *(float4*)(out + e) = o4;
}

extern "C" void kernel_launch(void* const* d_in, const int* in_sizes, int n_in,
                              void* d_out, int out_size) {
    (void)in_sizes; (void)n_in; (void)out_size;
    const float* x     = (const float*)d_in[0];
    const float* Wp    = (const float*)d_in[1];
    const float* bp    = (const float*)d_in[2];
    const float* Wc    = (const float*)d_in[3];
    const float* gamma = (const float*)d_in[4];
    const float* beta  = (const float*)d_in[5];
    float* out = (float*)d_out;

    cudaFuncSetAttribute(k_main, cudaFuncAttributeMaxDynamicSharedMemorySize, SMEM_BYTES);

    k_transpose<<<B_*H_, 256>>>(x);
    dim3 gmain(H_, B_, NS_);
    k_main<<<gmain, 128, SMEM_BYTES>>>(Wp, bp, Wc);
    dim3 gstats(64, NS_);
    k_stats<<<gstats, 256>>>(gamma, beta);
    int n4 = (B_*C_*HW_) / 4;
    k_final<<<(n4 + 255) / 256, 256>>>(out);
}